// round 7
// baseline (speedup 1.0000x reference)
#include <cuda_runtime.h>
#include <math.h>
#include <stdint.h>

// Problem constants
#define NB 4
#define NL 1024
#define ND 1024
#define NH 16
#define NDK 64

// ---------------------------------------------------------------------------
// Static device scratch (allocation-free rule: __device__ globals only).
// ---------------------------------------------------------------------------
__device__ float g_qh[NB * NH * NL * NDK];             // 16 MB  [B,H,L,DK]
__device__ float g_kh[NB * NH * NL * NDK];             // 16 MB
__device__ float g_vh[NB * NH * NL * NDK];             // 16 MB
__device__ float g_ctx[(size_t)NB * NL * ND];          // 16 MB  [B,L,H*DV]
__device__ float g_pre[(size_t)NB * NL * ND];          // 16 MB  pre-LN
__device__ float g_attn_fb[(size_t)NB * NH * NL * NL]; // 256 MB fallback attn

// ---------------------------------------------------------------------------
// TF32 helpers
// ---------------------------------------------------------------------------
__device__ __forceinline__ uint32_t f2tf32(float f) {
    uint32_t r;
    asm("cvt.rna.tf32.f32 %0, %1;" : "=r"(r) : "f"(f));
    return r;
}

__device__ __forceinline__ void mma_tf32(float d[4], const uint32_t a[4], const uint32_t b[2]) {
    asm volatile(
        "mma.sync.aligned.m16n8k8.row.col.f32.tf32.tf32.f32 "
        "{%0,%1,%2,%3}, {%4,%5,%6,%7}, {%8,%9}, {%0,%1,%2,%3};"
        : "+f"(d[0]), "+f"(d[1]), "+f"(d[2]), "+f"(d[3])
        : "r"(a[0]), "r"(a[1]), "r"(a[2]), "r"(a[3]), "r"(b[0]), "r"(b[1]));
}

// ---------------------------------------------------------------------------
// Pipelined TF32 mainloop: C[128,128] tile of A[.,1024] @ B[.,1024]^T (K-major).
// 256 threads = 8 warps (2m x 4n), warp tile 64x32, m16n8k8 frags.
// Register prefetch: next K-tile's LDGs fly while current tile's mmas issue.
// ---------------------------------------------------------------------------
__device__ __forceinline__ void tf32_mainloop_p(
    const float* __restrict__ A, const float* __restrict__ B,
    uint32_t (*As)[32], uint32_t (*Bs)[32], float acc[4][4][4])
{
    const int tid = threadIdx.x;
    const int lane = tid & 31;
    const int wid = tid >> 5;
    const int gid = lane >> 2;          // 0..7
    const int tig = lane & 3;           // 0..3
    const int wm = (wid >> 2) * 64;
    const int wn = (wid & 3) * 32;
    const int ldrow = tid >> 3;         // 0..31
    const int ldcol = (tid & 7) * 4;    // 0..28

    float4 pa[4], pb[4];
#pragma unroll
    for (int p = 0; p < 4; p++) {
        pa[p] = *(const float4*)(A + (size_t)(ldrow + p * 32) * 1024 + ldcol);
        pb[p] = *(const float4*)(B + (size_t)(ldrow + p * 32) * 1024 + ldcol);
    }
#pragma unroll
    for (int p = 0; p < 4; p++) {
        const int r = ldrow + p * 32;
        const int pc = ldcol ^ ((r & 7) * 4);
        *(uint4*)&As[r][pc] = make_uint4(f2tf32(pa[p].x), f2tf32(pa[p].y), f2tf32(pa[p].z), f2tf32(pa[p].w));
        *(uint4*)&Bs[r][pc] = make_uint4(f2tf32(pb[p].x), f2tf32(pb[p].y), f2tf32(pb[p].z), f2tf32(pb[p].w));
    }
    __syncthreads();

    for (int k0 = 32; k0 <= 1024; k0 += 32) {
        if (k0 < 1024) {                 // prefetch next tile
#pragma unroll
            for (int p = 0; p < 4; p++) {
                pa[p] = *(const float4*)(A + (size_t)(ldrow + p * 32) * 1024 + k0 + ldcol);
                pb[p] = *(const float4*)(B + (size_t)(ldrow + p * 32) * 1024 + k0 + ldcol);
            }
        }
#pragma unroll
        for (int ks = 0; ks < 4; ks++) {
            const int kb = ks * 8;
            uint32_t af[4][4], bf[4][2];
#pragma unroll
            for (int mt = 0; mt < 4; mt++) {
                const int m = wm + mt * 16 + gid;
                const int sx = (m & 7) * 4;
                af[mt][0] = As[m][(kb + tig) ^ sx];
                af[mt][1] = As[m + 8][(kb + tig) ^ sx];
                af[mt][2] = As[m][(kb + tig + 4) ^ sx];
                af[mt][3] = As[m + 8][(kb + tig + 4) ^ sx];
            }
#pragma unroll
            for (int nt = 0; nt < 4; nt++) {
                const int n = wn + nt * 8 + gid;
                const int sy = (n & 7) * 4;
                bf[nt][0] = Bs[n][(kb + tig) ^ sy];
                bf[nt][1] = Bs[n][(kb + tig + 4) ^ sy];
            }
#pragma unroll
            for (int mt = 0; mt < 4; mt++)
#pragma unroll
                for (int nt = 0; nt < 4; nt++)
                    mma_tf32(acc[mt][nt], af[mt], bf[nt]);
        }
        __syncthreads();
        if (k0 < 1024) {
#pragma unroll
            for (int p = 0; p < 4; p++) {
                const int r = ldrow + p * 32;
                const int pc = ldcol ^ ((r & 7) * 4);
                *(uint4*)&As[r][pc] = make_uint4(f2tf32(pa[p].x), f2tf32(pa[p].y), f2tf32(pa[p].z), f2tf32(pa[p].w));
                *(uint4*)&Bs[r][pc] = make_uint4(f2tf32(pb[p].x), f2tf32(pb[p].y), f2tf32(pb[p].z), f2tf32(pb[p].w));
            }
            __syncthreads();
        }
    }
}

// ---------------------------------------------------------------------------
// Kernel 1: projections via tf32 mma. blockIdx.z selects Q/K/V.
// ---------------------------------------------------------------------------
__global__ __launch_bounds__(256)
void proj_mma(const float* __restrict__ q, const float* __restrict__ k,
              const float* __restrict__ v,
              const float* __restrict__ w_q, const float* __restrict__ b_q,
              const float* __restrict__ w_k, const float* __restrict__ b_k,
              const float* __restrict__ w_v, const float* __restrict__ b_v)
{
    __shared__ uint32_t As[128][32];
    __shared__ uint32_t Bs[128][32];
    const int which = blockIdx.z;
    const float* X    = (which == 0) ? q   : (which == 1) ? k   : v;
    const float* W    = (which == 0) ? w_q : (which == 1) ? w_k : w_v;
    const float* bias = (which == 0) ? b_q : (which == 1) ? b_k : b_v;
    float* out        = (which == 0) ? g_qh : (which == 1) ? g_kh : g_vh;

    const int m0 = blockIdx.y * 128;
    const int n0 = blockIdx.x * 128;

    float acc[4][4][4];
#pragma unroll
    for (int i = 0; i < 4; i++)
#pragma unroll
        for (int j = 0; j < 4; j++)
#pragma unroll
            for (int c = 0; c < 4; c++) acc[i][j][c] = 0.0f;

    tf32_mainloop_p(X + (size_t)m0 * 1024, W + (size_t)n0 * 1024, As, Bs, acc);

    const int lane = threadIdx.x & 31;
    const int wid = threadIdx.x >> 5;
    const int gid = lane >> 2, tig = lane & 3;
    const int wm = (wid >> 2) * 64, wn = (wid & 3) * 32;
    const int bb = m0 >> 10;

#pragma unroll
    for (int mt = 0; mt < 4; mt++) {
        const int m = m0 + wm + mt * 16 + gid;
        const int l0 = m & (NL - 1);
        const int l1 = (m + 8) & (NL - 1);
#pragma unroll
        for (int nt = 0; nt < 4; nt++) {
            const int n = n0 + wn + nt * 8 + tig * 2;
            const int h = n >> 6;
            const int d = n & 63;
            float2 bi = *(const float2*)(bias + n);
            float* base = out + ((size_t)((bb * NH + h) * NL)) * NDK + d;
            *(float2*)(base + (size_t)l0 * NDK) =
                make_float2(acc[mt][nt][0] + bi.x, acc[mt][nt][1] + bi.y);
            *(float2*)(base + (size_t)l1 * NDK) =
                make_float2(acc[mt][nt][2] + bi.x, acc[mt][nt][3] + bi.y);
        }
    }
}

// ---------------------------------------------------------------------------
// Kernel 5: FC via tf32 mma. g_pre = g_ctx @ W^T + bias + resid
// ---------------------------------------------------------------------------
__global__ __launch_bounds__(256)
void fc_mma(const float* __restrict__ W, const float* __restrict__ bias,
            const float* __restrict__ resid)
{
    __shared__ uint32_t As[128][32];
    __shared__ uint32_t Bs[128][32];
    const int m0 = blockIdx.y * 128;
    const int n0 = blockIdx.x * 128;

    float acc[4][4][4];
#pragma unroll
    for (int i = 0; i < 4; i++)
#pragma unroll
        for (int j = 0; j < 4; j++)
#pragma unroll
            for (int c = 0; c < 4; c++) acc[i][j][c] = 0.0f;

    tf32_mainloop_p(g_ctx + (size_t)m0 * 1024, W + (size_t)n0 * 1024, As, Bs, acc);

    const int lane = threadIdx.x & 31;
    const int wid = threadIdx.x >> 5;
    const int gid = lane >> 2, tig = lane & 3;
    const int wm = (wid >> 2) * 64, wn = (wid & 3) * 32;

#pragma unroll
    for (int mt = 0; mt < 4; mt++) {
        const int m = m0 + wm + mt * 16 + gid;
#pragma unroll
        for (int nt = 0; nt < 4; nt++) {
            const int n = n0 + wn + nt * 8 + tig * 2;
            float2 bi = *(const float2*)(bias + n);
            float2 r0 = *(const float2*)(resid + (size_t)m * ND + n);
            float2 r1 = *(const float2*)(resid + (size_t)(m + 8) * ND + n);
            *(float2*)(g_pre + (size_t)m * ND + n) =
                make_float2(acc[mt][nt][0] + bi.x + r0.x, acc[mt][nt][1] + bi.y + r0.y);
            *(float2*)(g_pre + (size_t)(m + 8) * ND + n) =
                make_float2(acc[mt][nt][2] + bi.x + r1.x, acc[mt][nt][3] + bi.y + r1.y);
        }
    }
}

// ---------------------------------------------------------------------------
// Kernel 2+3 FUSED: scores (scale, gate, mask) + row softmax -> attn.
// Block = 16 q-rows x ALL 1024 k-cols of one (b,h). grid (qt=64, bh=64).
// 256 threads: ty = tid>>7 (2 row-groups of 8), tx = tid&127 (8 cols each).
// Thread holds its 8x8 score patch in registers through softmax.
// QK^T streamed over d in chunks of 4 (Ks[4][1024] = 16 KB smem).
// ---------------------------------------------------------------------------
__global__ __launch_bounds__(256)
void scores_softmax_kernel(const float* __restrict__ gate, const int* __restrict__ mask,
                           float* __restrict__ attn_ext, int use_ext)
{
    float* attn = use_ext ? attn_ext : g_attn_fb;
    __shared__ float Ks[4][NL];         // 16 KB
    __shared__ float Qs[16][4];
    __shared__ float red[16][4];        // per-row, per-warp partials

    const int tid = threadIdx.x;
    const int tx = tid & 127;
    const int ty = tid >> 7;
    const int lane = tid & 31;
    const int w4 = (tid >> 5) & 3;      // warp index within row-group
    const int qt = blockIdx.x;
    const int bh = blockIdx.y;
    const int b = bh >> 4;
    const float* Qp = g_qh + ((size_t)bh * NL + qt * 16) * NDK;
    const float* Kp = g_kh + (size_t)bh * NL * NDK;

    float acc[8][8];
#pragma unroll
    for (int i = 0; i < 8; i++)
#pragma unroll
        for (int j = 0; j < 8; j++) acc[i][j] = 0.0f;

    for (int dc = 0; dc < 16; dc++) {
        // load K chunk: all 1024 cols x 4 d-values
#pragma unroll
        for (int p = 0; p < 4; p++) {
            const int col = tid + p * 256;
            float4 kv = *(const float4*)(Kp + (size_t)col * NDK + dc * 4);
            Ks[0][col] = kv.x; Ks[1][col] = kv.y; Ks[2][col] = kv.z; Ks[3][col] = kv.w;
        }
        if (tid < 16) {
            float4 qv = *(const float4*)(Qp + (size_t)tid * NDK + dc * 4);
            Qs[tid][0] = qv.x; Qs[tid][1] = qv.y; Qs[tid][2] = qv.z; Qs[tid][3] = qv.w;
        }
        __syncthreads();
#pragma unroll
        for (int d = 0; d < 4; d++) {
            float aa[8];
#pragma unroll
            for (int i = 0; i < 8; i++) aa[i] = Qs[ty * 8 + i][d];
            float4 b0 = *(const float4*)&Ks[d][tx * 8];
            float4 b1 = *(const float4*)&Ks[d][tx * 8 + 4];
            float bb[8] = {b0.x, b0.y, b0.z, b0.w, b1.x, b1.y, b1.z, b1.w};
#pragma unroll
            for (int i = 0; i < 8; i++)
#pragma unroll
                for (int j = 0; j < 8; j++)
                    acc[i][j] = fmaf(aa[i], bb[j], acc[i][j]);
        }
        __syncthreads();
    }

    // scale * gate, mask -> logits (in regs)
#pragma unroll
    for (int i = 0; i < 8; i++) {
        const int qi = qt * 16 + ty * 8 + i;
        const size_t rowg = ((size_t)bh * NL + qi) * NL + tx * 8;
        const size_t rowm = ((size_t)b * NL + qi) * NL + tx * 8;
        float4 g0 = *(const float4*)(gate + rowg);
        float4 g1 = *(const float4*)(gate + rowg + 4);
        int4 k0 = *(const int4*)(mask + rowm);
        int4 k1 = *(const int4*)(mask + rowm + 4);
        float ga[8] = {g0.x, g0.y, g0.z, g0.w, g1.x, g1.y, g1.z, g1.w};
        int ma[8] = {k0.x, k0.y, k0.z, k0.w, k1.x, k1.y, k1.z, k1.w};
#pragma unroll
        for (int j = 0; j < 8; j++)
            acc[i][j] = (ma[j] > 0) ? -INFINITY : acc[i][j] * 0.125f * ga[j];
    }

    // row max: local -> warp shfl -> cross-warp via red[16][4]
    float rmax[8];
#pragma unroll
    for (int i = 0; i < 8; i++) {
        float m = acc[i][0];
#pragma unroll
        for (int j = 1; j < 8; j++) m = fmaxf(m, acc[i][j]);
#pragma unroll
        for (int o = 16; o; o >>= 1) m = fmaxf(m, __shfl_xor_sync(0xffffffffu, m, o));
        if (lane == 0) red[ty * 8 + i][w4] = m;
    }
    __syncthreads();
#pragma unroll
    for (int i = 0; i < 8; i++) {
        const int rr = ty * 8 + i;
        rmax[i] = fmaxf(fmaxf(red[rr][0], red[rr][1]), fmaxf(red[rr][2], red[rr][3]));
    }
    __syncthreads();                    // everyone done reading red before sum reuse

    // exp + row sum (same reduction path)
    float lsum[8];
#pragma unroll
    for (int i = 0; i < 8; i++) {
        float s = 0.0f;
        if (rmax[i] == -INFINITY) {     // fully-masked row -> all zeros
#pragma unroll
            for (int j = 0; j < 8; j++) acc[i][j] = 0.0f;
        } else {
#pragma unroll
            for (int j = 0; j < 8; j++) {
                acc[i][j] = expf(acc[i][j] - rmax[i]);
                s += acc[i][j];
            }
        }
#pragma unroll
        for (int o = 16; o; o >>= 1) s += __shfl_xor_sync(0xffffffffu, s, o);
        if (lane == 0) red[ty * 8 + i][w4] = s;
        lsum[i] = s;                    // placeholder; final below
    }
    __syncthreads();
#pragma unroll
    for (int i = 0; i < 8; i++) {
        const int rr = ty * 8 + i;
        const float tot = red[rr][0] + red[rr][1] + red[rr][2] + red[rr][3];
        lsum[i] = (tot > 0.0f) ? 1.0f / tot : 0.0f;
    }

    // normalized write, coalesced float4
#pragma unroll
    for (int i = 0; i < 8; i++) {
        const int qi = qt * 16 + ty * 8 + i;
        float* dst = attn + ((size_t)bh * NL + qi) * NL + tx * 8;
        const float r = lsum[i];
        *(float4*)dst = make_float4(acc[i][0] * r, acc[i][1] * r, acc[i][2] * r, acc[i][3] * r);
        *(float4*)(dst + 4) = make_float4(acc[i][4] * r, acc[i][5] * r, acc[i][6] * r, acc[i][7] * r);
    }
}

// ---------------------------------------------------------------------------
// Kernel 4: ctx = attn @ Vh per (b,h) via TF32 mma, register-prefetch pipeline.
// Block: 128 q-rows x 64 (full DV). 8 warps (4m x 2n). grid (8, 64).
// ---------------------------------------------------------------------------
__global__ __launch_bounds__(256)
void pv_mma(const float* __restrict__ attn_ext, int use_ext)
{
    const float* attn = use_ext ? attn_ext : g_attn_fb;
    __shared__ uint32_t As[128][32];
    __shared__ uint32_t Vs[64][32];
    const int tid = threadIdx.x;
    const int lane = tid & 31, wid = tid >> 5;
    const int gid = lane >> 2, tig = lane & 3;
    const int wm = (wid >> 1) * 32;
    const int wn = (wid & 1) * 32;
    const int m0 = blockIdx.x * 128;
    const int bh = blockIdx.y;
    const int b = bh >> 4, h = bh & 15;
    const float* Ap = attn + ((size_t)bh * NL + m0) * NL;
    const float* Vp = g_vh + (size_t)bh * NL * NDK;
    const int ldrow = tid >> 3, ldcol = (tid & 7) * 4;
    const int vrow = tid >> 3, vcol = (tid & 7) * 8;

    float acc[2][4][4];
#pragma unroll
    for (int i = 0; i < 2; i++)
#pragma unroll
        for (int j = 0; j < 4; j++)
#pragma unroll
            for (int c = 0; c < 4; c++) acc[i][j][c] = 0.0f;

    float4 pa[4], pv0, pv1;
#pragma unroll
    for (int p = 0; p < 4; p++)
        pa[p] = *(const float4*)(Ap + (size_t)(ldrow + p * 32) * NL + ldcol);
    pv0 = *(const float4*)(Vp + (size_t)vrow * NDK + vcol);
    pv1 = *(const float4*)(Vp + (size_t)vrow * NDK + vcol + 4);
#pragma unroll
    for (int p = 0; p < 4; p++) {
        const int r = ldrow + p * 32;
        const int pc = ldcol ^ ((r & 7) * 4);
        *(uint4*)&As[r][pc] = make_uint4(f2tf32(pa[p].x), f2tf32(pa[p].y), f2tf32(pa[p].z), f2tf32(pa[p].w));
    }
#pragma unroll
    for (int i = 0; i < 4; i++) {
        Vs[vcol + i][vrow ^ (i * 4)] = f2tf32((&pv0.x)[i]);
        Vs[vcol + 4 + i][vrow ^ ((i + 4) * 4)] = f2tf32((&pv1.x)[i]);
    }
    __syncthreads();

    for (int k0 = 32; k0 <= 1024; k0 += 32) {
        if (k0 < 1024) {
#pragma unroll
            for (int p = 0; p < 4; p++)
                pa[p] = *(const float4*)(Ap + (size_t)(ldrow + p * 32) * NL + k0 + ldcol);
            pv0 = *(const float4*)(Vp + (size_t)(k0 + vrow) * NDK + vcol);
            pv1 = *(const float4*)(Vp + (size_t)(k0 + vrow) * NDK + vcol + 4);
        }
#pragma unroll
        for (int ks = 0; ks < 4; ks++) {
            const int kb = ks * 8;
            uint32_t af[2][4], bf[4][2];
#pragma unroll
            for (int mt = 0; mt < 2; mt++) {
                const int m = wm + mt * 16 + gid;
                const int sx = (m & 7) * 4;
                af[mt][0] = As[m][(kb + tig) ^ sx];
                af[mt][1] = As[m + 8][(kb + tig) ^ sx];
                af[mt][2] = As[m][(kb + tig + 4) ^ sx];
                af[mt][3] = As[m + 8][(kb + tig + 4) ^ sx];
            }
#pragma unroll
            for (int nt = 0; nt < 4; nt++) {
                const int n = wn + nt * 8 + gid;
                const int sy = (n & 7) * 4;
                bf[nt][0] = Vs[n][(kb + tig) ^ sy];
                bf[nt][1] = Vs[n][(kb + tig + 4) ^ sy];
            }
#pragma unroll
            for (int mt = 0; mt < 2; mt++)
#pragma unroll
                for (int nt = 0; nt < 4; nt++)
                    mma_tf32(acc[mt][nt], af[mt], bf[nt]);
        }
        __syncthreads();
        if (k0 < 1024) {
#pragma unroll
            for (int p = 0; p < 4; p++) {
                const int r = ldrow + p * 32;
                const int pc = ldcol ^ ((r & 7) * 4);
                *(uint4*)&As[r][pc] = make_uint4(f2tf32(pa[p].x), f2tf32(pa[p].y), f2tf32(pa[p].z), f2tf32(pa[p].w));
            }
#pragma unroll
            for (int i = 0; i < 4; i++) {
                Vs[vcol + i][vrow ^ (i * 4)] = f2tf32((&pv0.x)[i]);
                Vs[vcol + 4 + i][vrow ^ ((i + 4) * 4)] = f2tf32((&pv1.x)[i]);
            }
            __syncthreads();
        }
    }

#pragma unroll
    for (int mt = 0; mt < 2; mt++) {
        const int m = m0 + wm + mt * 16 + gid;
#pragma unroll
        for (int nt = 0; nt < 4; nt++) {
            const int nn = wn + nt * 8 + tig * 2;
            *(float2*)(g_ctx + ((size_t)(b * NL + m)) * ND + h * NDK + nn) =
                make_float2(acc[mt][nt][0], acc[mt][nt][1]);
            *(float2*)(g_ctx + ((size_t)(b * NL + m + 8)) * ND + h * NDK + nn) =
                make_float2(acc[mt][nt][2], acc[mt][nt][3]);
        }
    }
}

// ---------------------------------------------------------------------------
// Kernel 6: LayerNorm over d_model, one block per row of g_pre -> d_out
// ---------------------------------------------------------------------------
__global__ __launch_bounds__(256)
void ln_kernel(const float* __restrict__ g, const float* __restrict__ beta,
               float* __restrict__ out)
{
    __shared__ float sred[8];
    __shared__ float sred2[8];
    __shared__ float bmu, brstd;
    const int t = threadIdx.x;
    const size_t row = blockIdx.x;
    const float4* p = (const float4*)(g_pre + row * ND);
    float4 v = p[t];

    float s = v.x + v.y + v.z + v.w;
    float sq = v.x * v.x + v.y * v.y + v.z * v.z + v.w * v.w;
#pragma unroll
    for (int o = 16; o; o >>= 1) {
        s += __shfl_xor_sync(0xffffffffu, s, o);
        sq += __shfl_xor_sync(0xffffffffu, sq, o);
    }
    if ((t & 31) == 0) { sred[t >> 5] = s; sred2[t >> 5] = sq; }
    __syncthreads();
    if (t < 32) {
        float s2 = (t < 8) ? sred[t] : 0.0f;
        float q2 = (t < 8) ? sred2[t] : 0.0f;
#pragma unroll
        for (int o = 4; o; o >>= 1) {
            s2 += __shfl_xor_sync(0xffffffffu, s2, o);
            q2 += __shfl_xor_sync(0xffffffffu, q2, o);
        }
        if (t == 0) {
            const float mu = s2 * (1.0f / ND);
            const float var = q2 * (1.0f / ND) - mu * mu;
            bmu = mu;
            brstd = rsqrtf(var + 1e-5f);
        }
    }
    __syncthreads();
    const float mu = bmu, rstd = brstd;
    float4 gg = ((const float4*)g)[t];
    float4 bb = ((const float4*)beta)[t];
    float4 o4;
    o4.x = (v.x - mu) * rstd * gg.x + bb.x;
    o4.y = (v.y - mu) * rstd * gg.y + bb.y;
    o4.z = (v.z - mu) * rstd * gg.z + bb.z;
    o4.w = (v.w - mu) * rstd * gg.w + bb.w;
    ((float4*)(out + row * ND))[t] = o4;
}

// ---------------------------------------------------------------------------
// Launcher — kernel launches ONLY
// ---------------------------------------------------------------------------
extern "C" void kernel_launch(void* const* d_in, const int* in_sizes, int n_in,
                              void* d_out, int out_size)
{
    const float* q    = (const float*)d_in[0];
    const float* k    = (const float*)d_in[1];
    const float* v    = (const float*)d_in[2];
    const int*   mask = (const int*)  d_in[3];
    const float* gate = (const float*)d_in[4];
    const float* w_q  = (const float*)d_in[5];
    const float* b_q  = (const float*)d_in[6];
    const float* w_k  = (const float*)d_in[7];
    const float* b_k  = (const float*)d_in[8];
    const float* w_v  = (const float*)d_in[9];
    const float* b_v  = (const float*)d_in[10];
    const float* w_fc = (const float*)d_in[11];
    const float* b_fc = (const float*)d_in[12];
    const float* ln_g = (const float*)d_in[13];
    const float* ln_b = (const float*)d_in[14];

    const long long OUTN = 4LL * 1024 * 1024;        // out elements
    const long long ATTN = 64LL * 1024 * 1024;       // attn elements
    const int use_ext = ((long long)out_size >= OUTN + ATTN) ? 1 : 0;
    float* attn_ext = (float*)d_out + OUTN;

    // 1) Q/K/V projections (pipelined tf32 mma)
    proj_mma<<<dim3(8, 32, 3), 256>>>(q, k, v, w_q, b_q, w_k, b_k, w_v, b_v);
    // 2+3) fused scores + gate + mask + softmax -> attn
    scores_softmax_kernel<<<dim3(64, 64), 256>>>(gate, mask, attn_ext, use_ext);
    // 4) P @ V (pipelined tf32 mma) -> g_ctx
    pv_mma<<<dim3(8, 64), 256>>>(attn_ext, use_ext);
    // 5) FC (pipelined tf32 mma) + bias + residual -> g_pre
    fc_mma<<<dim3(8, 32), 256>>>(w_fc, b_fc, q);
    // 6) LayerNorm -> d_out[0 : 4M]
    ln_kernel<<<4096, 256>>>(ln_g, ln_b, (float*)d_out);
}